// round 1
// baseline (speedup 1.0000x reference)
#include <cuda_runtime.h>

#define G    64
#define FOLD 256
#define HID  128

// Scratch (device globals — no runtime allocation allowed).
__device__ float g_e[1000000];          // exp(score) per row; [prot | lig | cross]
__device__ float g_num[3 * G * FOLD];   // weighted-sum numerators per pool
__device__ float g_den[3 * G];          // softmax denominators per pool

// ---------------------------------------------------------------------------
__global__ void zero_kernel() {
    int i = blockIdx.x * blockDim.x + threadIdx.x;
    if (i < 3 * G * FOLD) g_num[i] = 0.f;
    if (i < 3 * G)        g_den[i] = 0.f;
}

// ---------------------------------------------------------------------------
// scores: e[row] = exp( relu(x @ W1 + b1) @ W2 + b2 )
// Tiled SGEMM: 64 rows x 128 hidden, K=256, BK=32, 256 threads,
// each thread computes a 4x8 register tile, then epilogue reduces to a scalar
// score per row via half-warp shuffles.
__global__ __launch_bounds__(256) void scores_kernel(
    const float* __restrict__ x, int N,
    const float* __restrict__ W1, const float* __restrict__ b1,
    const float* __restrict__ W2, const float* __restrict__ b2,
    int e_off)
{
    __shared__ float As[64][36];    // padded: stride 36 floats keeps banks spread
    __shared__ float Bs[32][128];

    const int tid  = threadIdx.x;
    const int row0 = blockIdx.x * 64;
    const int tn   = tid & 15;      // 16 col-groups of 8
    const int tm   = tid >> 4;      // 16 row-groups of 4

    float acc[4][8];
#pragma unroll
    for (int i = 0; i < 4; i++)
#pragma unroll
        for (int j = 0; j < 8; j++) acc[i][j] = 0.f;

    for (int kk = 0; kk < FOLD; kk += 32) {
        // load 64x32 x-tile (512 float4, 2 per thread)
#pragma unroll
        for (int l = 0; l < 2; l++) {
            int e  = tid + l * 256;
            int r  = e >> 3;
            int kq = e & 7;
            float4 v = make_float4(0.f, 0.f, 0.f, 0.f);
            int grow = row0 + r;
            if (grow < N)
                v = *(const float4*)(x + (size_t)grow * FOLD + kk + kq * 4);
            *(float4*)&As[r][kq * 4] = v;
        }
        // load 32x128 W1-tile (1024 float4, 4 per thread)
#pragma unroll
        for (int l = 0; l < 4; l++) {
            int e  = tid + l * 256;
            int k  = e >> 5;
            int nq = e & 31;
            *(float4*)&Bs[k][nq * 4] =
                *(const float4*)(W1 + (size_t)(kk + k) * HID + nq * 4);
        }
        __syncthreads();

#pragma unroll
        for (int k = 0; k < 32; k++) {
            float a[4], b[8];
#pragma unroll
            for (int i = 0; i < 4; i++) a[i] = As[tm * 4 + i][k];
#pragma unroll
            for (int j = 0; j < 8; j++) b[j] = Bs[k][tn * 8 + j];
#pragma unroll
            for (int i = 0; i < 4; i++)
#pragma unroll
                for (int j = 0; j < 8; j++)
                    acc[i][j] = fmaf(a[i], b[j], acc[i][j]);
        }
        __syncthreads();
    }

    // epilogue: relu + second linear, reduce over the 16 tn-threads (half-warp)
    float bb1[8], w2v[8];
#pragma unroll
    for (int j = 0; j < 8; j++) {
        bb1[j] = b1[tn * 8 + j];
        w2v[j] = W2[tn * 8 + j];
    }
    const float b2v = b2[0];

#pragma unroll
    for (int i = 0; i < 4; i++) {
        float p = 0.f;
#pragma unroll
        for (int j = 0; j < 8; j++) {
            float h = acc[i][j] + bb1[j];
            p = fmaf(fmaxf(h, 0.f), w2v[j], p);
        }
#pragma unroll
        for (int off = 8; off > 0; off >>= 1)
            p += __shfl_down_sync(0xffffffffu, p, off, 16);
        if (tn == 0) {
            int grow = row0 + tm * 4 + i;
            if (grow < N) g_e[e_off + grow] = expf(p + b2v);
        }
    }
}

// ---------------------------------------------------------------------------
// Pooling for SORTED segment ids (protein / ligand): contiguous segments,
// register accumulator per column, flush on segment change.
__global__ __launch_bounds__(256) void pool_sorted_kernel(
    const float* __restrict__ x, const int* __restrict__ batch, int N,
    int e_off, int pool, int rpb)
{
    const int c  = threadIdx.x;
    int r0   = blockIdx.x * rpb;
    if (r0 >= N) return;
    int rend = min(N, r0 + rpb);

    float* num = g_num + pool * G * FOLD;
    float* den = g_den + pool * G;

    int   cur  = __ldg(batch + r0);
    float acc  = 0.f, dacc = 0.f;

    for (int row = r0; row < rend; ++row) {
        int   sg = __ldg(batch + row);
        float ev = g_e[e_off + row];
        if (sg != cur) {
            atomicAdd(num + cur * FOLD + c, acc);
            if (c == 0) atomicAdd(den + cur, dacc);
            acc = 0.f; dacc = 0.f; cur = sg;
        }
        acc  = fmaf(ev, x[(size_t)row * FOLD + c], acc);
        dacc += ev;
    }
    atomicAdd(num + cur * FOLD + c, acc);
    if (c == 0) atomicAdd(den + cur, dacc);
}

// ---------------------------------------------------------------------------
// Pooling for RANDOM segment ids (cross edges): shared [64 segs x 128 cols]
// accumulator, thread c is the exclusive owner of column c (no atomics in
// the loop). grid.y in {0,1} selects the 128-column half.
__global__ __launch_bounds__(128) void pool_cross_kernel(
    const float* __restrict__ x, const int* __restrict__ ci0,
    const int* __restrict__ lb, int N, int e_off, int rpb)
{
    __shared__ float accs[G * 128];
    __shared__ float dens[G];

    const int c  = threadIdx.x;
    const int cb = blockIdx.y * 128;

    for (int i = c; i < G * 128; i += 128) accs[i] = 0.f;
    if (c < G) dens[c] = 0.f;
    __syncthreads();

    int r0   = blockIdx.x * rpb;
    int rend = min(N, r0 + rpb);

    for (int row = r0; row < rend; ++row) {
        float ev = g_e[e_off + row];
        int   sg = __ldg(lb + __ldg(ci0 + row));
        float xv = x[(size_t)row * FOLD + cb + c];
        accs[sg * 128 + c] += ev * xv;
        if (c == 0 && blockIdx.y == 0) dens[sg] += ev;
    }
    __syncthreads();

    float* num = g_num + 2 * G * FOLD;
    for (int i = c; i < G * 128; i += 128) {
        int sg = i >> 7, cc = i & 127;
        float v = accs[i];
        if (v != 0.f) atomicAdd(num + sg * FOLD + cb + cc, v);
    }
    if (blockIdx.y == 0 && c < G) atomicAdd(g_den + 2 * G + c, dens[c]);
}

// ---------------------------------------------------------------------------
// Finalize: pooled = num/den, concat [G,768], 2-layer MLP + linear head.
__global__ __launch_bounds__(256) void mlp_kernel(
    const float* __restrict__ W1, const float* __restrict__ b1,
    const float* __restrict__ W2, const float* __restrict__ b2,
    const float* __restrict__ oW, const float* __restrict__ ob,
    float* __restrict__ out)
{
    __shared__ float comb[3 * FOLD];
    __shared__ float h1s[FOLD];
    __shared__ float h2s[HID];
    __shared__ float red[4];

    const int g = blockIdx.x, t = threadIdx.x;

    for (int i = t; i < 3 * FOLD; i += 256) {
        int p = i >> 8, cc = i & 255;
        comb[i] = g_num[(p * G + g) * FOLD + cc] / g_den[p * G + g];
    }
    __syncthreads();

    float h = b1[t];
    for (int k = 0; k < 3 * FOLD; k++)
        h = fmaf(comb[k], W1[(size_t)k * FOLD + t], h);
    h1s[t] = fmaxf(h, 0.f);
    __syncthreads();

    if (t < HID) {
        float h2 = b2[t];
        for (int k = 0; k < FOLD; k++)
            h2 = fmaf(h1s[k], W2[(size_t)k * HID + t], h2);
        h2s[t] = fmaxf(h2, 0.f);
    }
    __syncthreads();

    if (t < HID) {
        float v = h2s[t] * oW[t];
#pragma unroll
        for (int off = 16; off > 0; off >>= 1)
            v += __shfl_down_sync(0xffffffffu, v, off);
        if ((t & 31) == 0) red[t >> 5] = v;
    }
    __syncthreads();
    if (t == 0) out[g] = red[0] + red[1] + red[2] + red[3] + ob[0];
}

// ---------------------------------------------------------------------------
extern "C" void kernel_launch(void* const* d_in, const int* in_sizes, int n_in,
                              void* d_out, int out_size)
{
    const float* rec   = (const float*)d_in[0];
    const float* lig   = (const float*)d_in[1];
    const float* cross = (const float*)d_in[2];
    const int*   cidx  = (const int*)d_in[3];   // [2, N_cross]; row 0 first
    const int*   pb    = (const int*)d_in[4];
    const int*   lb    = (const int*)d_in[5];
    // d_in[6] = num_graphs (fixed at 64 for this problem)
    const float* paW1 = (const float*)d_in[7];
    const float* pab1 = (const float*)d_in[8];
    const float* paW2 = (const float*)d_in[9];
    const float* pab2 = (const float*)d_in[10];
    const float* laW1 = (const float*)d_in[11];
    const float* lab1 = (const float*)d_in[12];
    const float* laW2 = (const float*)d_in[13];
    const float* lab2 = (const float*)d_in[14];
    const float* caW1 = (const float*)d_in[15];
    const float* cab1 = (const float*)d_in[16];
    const float* caW2 = (const float*)d_in[17];
    const float* cab2 = (const float*)d_in[18];
    const float* mW1  = (const float*)d_in[19];
    const float* mb1  = (const float*)d_in[20];
    const float* mW2  = (const float*)d_in[21];
    const float* mb2  = (const float*)d_in[22];
    const float* oW   = (const float*)d_in[23];
    const float* ob   = (const float*)d_in[24];

    float* out = (float*)d_out;

    const int Np = in_sizes[0] / FOLD;
    const int Nl = in_sizes[1] / FOLD;
    const int Nc = in_sizes[2] / FOLD;
    const int eo_p = 0, eo_l = Np, eo_c = Np + Nl;

    zero_kernel<<<(3 * G * FOLD + 255) / 256, 256>>>();

    scores_kernel<<<(Np + 63) / 64, 256>>>(rec,   Np, paW1, pab1, paW2, pab2, eo_p);
    scores_kernel<<<(Nl + 63) / 64, 256>>>(lig,   Nl, laW1, lab1, laW2, lab2, eo_l);
    scores_kernel<<<(Nc + 63) / 64, 256>>>(cross, Nc, caW1, cab1, caW2, cab2, eo_c);

    const int rpb_s = 2048;
    pool_sorted_kernel<<<(Np + rpb_s - 1) / rpb_s, 256>>>(rec, pb, Np, eo_p, 0, rpb_s);
    pool_sorted_kernel<<<(Nl + rpb_s - 1) / rpb_s, 256>>>(lig, lb, Nl, eo_l, 1, rpb_s);

    const int rpb_c = 4096;
    dim3 gc((Nc + rpb_c - 1) / rpb_c, 2);
    pool_cross_kernel<<<gc, 128>>>(cross, cidx, lb, Nc, eo_c, rpb_c);

    mlp_kernel<<<G, 256>>>(mW1, mb1, mW2, mb2, oW, ob, out);
}

// round 2
// speedup vs baseline: 4.4512x; 4.4512x over previous
#include <cuda_runtime.h>
#include <cuda_bf16.h>
#include <cstdint>

#define G    64
#define FOLD 256
#define HID  128

// Scratch (device globals — no runtime allocation allowed).
__device__ float g_e[1000000];          // exp(score) per row; [prot | lig | cross]
__device__ float g_num[3 * G * FOLD];   // weighted-sum numerators per pool
__device__ float g_den[3 * G];          // softmax denominators per pool

// ---------------------------------------------------------------------------
__global__ void zero_kernel() {
    int i = blockIdx.x * blockDim.x + threadIdx.x;
    if (i < 3 * G * FOLD) g_num[i] = 0.f;
    if (i < 3 * G)        g_den[i] = 0.f;
}

__device__ __forceinline__ uint32_t smem_u32(const void* p) {
    return (uint32_t)__cvta_generic_to_shared(p);
}

__device__ __forceinline__ uint32_t pack_bf16x2(float a, float b) {
    __nv_bfloat162 h = __floats2bfloat162_rn(a, b);
    return *reinterpret_cast<uint32_t*>(&h);
}

// ---------------------------------------------------------------------------
// scores via bf16 tensor cores:
//   e[row] = exp( relu(x @ W1 + b1) @ W2 + b2 )
// Block: 128 rows x 128 hidden, K=256 in two 128-wide tiles.
// 8 warps, each warp: m16 x n128 via mma.sync.m16n8k16 (bf16 in, f32 acc).
// Smem tiles are bf16 with 16B-chunk XOR swizzle for conflict-free ldmatrix.
__global__ __launch_bounds__(256) void scores_mma_kernel(
    const float* __restrict__ x, int N,
    const float* __restrict__ W1, const float* __restrict__ b1,
    const float* __restrict__ W2, const float* __restrict__ b2,
    int e_off)
{
    extern __shared__ char smem[];
    char*  As  = smem;                    // 128 rows x 128 bf16 (256B/row), 32KB
    char*  Bs  = smem + 32768;            // 128 k    x 128 n    (256B/row), 32KB
    float* b1s = (float*)(smem + 65536);  // 128 f32
    float* w2s = (float*)(smem + 66048);  // 128 f32

    const int tid  = threadIdx.x;
    const int lane = tid & 31;
    const int warp = tid >> 5;
    const int row0 = blockIdx.x * 128;

    if (tid < 128) { b1s[tid] = b1[tid]; w2s[tid] = W2[tid]; }

    float acc[16][4];
#pragma unroll
    for (int nt = 0; nt < 16; nt++)
#pragma unroll
        for (int j = 0; j < 4; j++) acc[nt][j] = 0.f;

    const uint32_t as_base = smem_u32(As);
    const uint32_t bs_base = smem_u32(Bs);
    const int m0 = warp * 16;

    for (int kt = 0; kt < 2; kt++) {
        __syncthreads();   // smem tiles free (also publishes b1s/w2s on kt=0)

        // Load x tile: 128 rows x 128 k, fp32 -> bf16, 16B chunks, swizzled.
#pragma unroll
        for (int i = 0; i < 8; i++) {
            int id = tid + i * 256;        // 2048 chunks
            int r  = id >> 4;              // row 0..127
            int kc = id & 15;              // 16B chunk (8 bf16)
            uint4 val = make_uint4(0u, 0u, 0u, 0u);
            int grow = row0 + r;
            if (grow < N) {
                const float4* p = (const float4*)(x + (size_t)grow * FOLD + kt * 128 + kc * 8);
                float4 f0 = p[0], f1 = p[1];
                val.x = pack_bf16x2(f0.x, f0.y);
                val.y = pack_bf16x2(f0.z, f0.w);
                val.z = pack_bf16x2(f1.x, f1.y);
                val.w = pack_bf16x2(f1.z, f1.w);
            }
            *(uint4*)(As + r * 256 + ((kc ^ (r & 7)) << 4)) = val;
        }
        // Load W1 tile: 128 k x 128 n.
#pragma unroll
        for (int i = 0; i < 8; i++) {
            int id = tid + i * 256;
            int k  = id >> 4;
            int nc = id & 15;
            const float4* p = (const float4*)(W1 + (size_t)(kt * 128 + k) * HID + nc * 8);
            float4 f0 = p[0], f1 = p[1];
            uint4 val;
            val.x = pack_bf16x2(f0.x, f0.y);
            val.y = pack_bf16x2(f0.z, f0.w);
            val.z = pack_bf16x2(f1.x, f1.y);
            val.w = pack_bf16x2(f1.z, f1.w);
            *(uint4*)(Bs + k * 256 + ((nc ^ (k & 7)) << 4)) = val;
        }
        __syncthreads();

#pragma unroll
        for (int ks = 0; ks < 8; ks++) {
            const int k0 = ks * 16;
            uint32_t a0, a1, a2, a3;
            {
                int r  = m0 + (lane & 7) + ((lane >> 3) & 1) * 8;
                int kc = (k0 >> 3) + (lane >> 4);
                uint32_t addr = as_base + r * 256 + ((kc ^ (r & 7)) << 4);
                asm volatile(
                    "ldmatrix.sync.aligned.m8n8.x4.shared.b16 {%0,%1,%2,%3}, [%4];"
                    : "=r"(a0), "=r"(a1), "=r"(a2), "=r"(a3) : "r"(addr));
            }
#pragma unroll
            for (int nt = 0; nt < 16; nt++) {
                uint32_t bf0, bf1;
                int kr = k0 + (lane & 15);
                uint32_t addr = bs_base + kr * 256 + ((nt ^ (kr & 7)) << 4);
                asm volatile(
                    "ldmatrix.sync.aligned.m8n8.x2.trans.shared.b16 {%0,%1}, [%2];"
                    : "=r"(bf0), "=r"(bf1) : "r"(addr));
                asm volatile(
                    "mma.sync.aligned.m16n8k16.row.col.f32.bf16.bf16.f32 "
                    "{%0,%1,%2,%3}, {%4,%5,%6,%7}, {%8,%9}, {%0,%1,%2,%3};"
                    : "+f"(acc[nt][0]), "+f"(acc[nt][1]), "+f"(acc[nt][2]), "+f"(acc[nt][3])
                    : "r"(a0), "r"(a1), "r"(a2), "r"(a3), "r"(bf0), "r"(bf1));
            }
        }
    }

    // Epilogue: relu + second linear + reduce 4 lanes -> score -> exp.
    // D frag: lane holds rows r1=(lane>>2), r2=r1+8; cols (lane&3)*2 + {0,1} per n-tile.
    const float b2v = b2[0];
    float p1 = 0.f, p2 = 0.f;
    const int cb = (lane & 3) * 2;
#pragma unroll
    for (int nt = 0; nt < 16; nt++) {
        int c = nt * 8 + cb;
        float w0 = w2s[c], w1v = w2s[c + 1];
        float q0 = b1s[c], q1 = b1s[c + 1];
        p1 += fmaxf(acc[nt][0] + q0, 0.f) * w0 + fmaxf(acc[nt][1] + q1, 0.f) * w1v;
        p2 += fmaxf(acc[nt][2] + q0, 0.f) * w0 + fmaxf(acc[nt][3] + q1, 0.f) * w1v;
    }
    p1 += __shfl_xor_sync(0xffffffffu, p1, 1);
    p1 += __shfl_xor_sync(0xffffffffu, p1, 2);
    p2 += __shfl_xor_sync(0xffffffffu, p2, 1);
    p2 += __shfl_xor_sync(0xffffffffu, p2, 2);
    if ((lane & 3) == 0) {
        int r1 = row0 + m0 + (lane >> 2);
        int r2 = r1 + 8;
        if (r1 < N) g_e[e_off + r1] = expf(p1 + b2v);
        if (r2 < N) g_e[e_off + r2] = expf(p2 + b2v);
    }
}

// ---------------------------------------------------------------------------
// Pooling for SORTED segment ids (protein / ligand): contiguous segments,
// register accumulator per column, flush on segment change. 4-row prefetch.
__global__ __launch_bounds__(256) void pool_sorted_kernel(
    const float* __restrict__ x, const int* __restrict__ batch, int N,
    int e_off, int pool, int rpb)
{
    const int c  = threadIdx.x;
    int r0 = blockIdx.x * rpb;
    if (r0 >= N) return;
    int rend = min(N, r0 + rpb);

    float* num = g_num + pool * G * FOLD;
    float* den = g_den + pool * G;

    int   cur = __ldg(batch + r0);
    float acc = 0.f, dacc = 0.f;

    int row = r0;
    for (; row + 4 <= rend; row += 4) {
        float ev[4], xv[4];
        int   sg[4];
#pragma unroll
        for (int j = 0; j < 4; j++) {
            sg[j] = __ldg(batch + row + j);
            ev[j] = g_e[e_off + row + j];
            xv[j] = x[(size_t)(row + j) * FOLD + c];
        }
#pragma unroll
        for (int j = 0; j < 4; j++) {
            if (sg[j] != cur) {
                atomicAdd(num + cur * FOLD + c, acc);
                if (c == 0) atomicAdd(den + cur, dacc);
                acc = 0.f; dacc = 0.f; cur = sg[j];
            }
            acc  = fmaf(ev[j], xv[j], acc);
            dacc += ev[j];
        }
    }
    for (; row < rend; ++row) {
        int   sg = __ldg(batch + row);
        float ev = g_e[e_off + row];
        float xv = x[(size_t)row * FOLD + c];
        if (sg != cur) {
            atomicAdd(num + cur * FOLD + c, acc);
            if (c == 0) atomicAdd(den + cur, dacc);
            acc = 0.f; dacc = 0.f; cur = sg;
        }
        acc  = fmaf(ev, xv, acc);
        dacc += ev;
    }
    atomicAdd(num + cur * FOLD + c, acc);
    if (c == 0) atomicAdd(den + cur, dacc);
}

// ---------------------------------------------------------------------------
// Pooling for RANDOM segment ids (cross edges): dynamic-smem [64 x 256]
// accumulator, thread c owns column c exclusively. 4-row prefetch.
__global__ __launch_bounds__(256) void pool_cross_kernel(
    const float* __restrict__ x, const int* __restrict__ ci0,
    const int* __restrict__ lb, int N, int e_off, int rpb)
{
    extern __shared__ float shm[];
    float* accs = shm;            // G*256
    float* dens = shm + G * 256;  // G

    const int c = threadIdx.x;
    for (int i = c; i < G * 256; i += 256) accs[i] = 0.f;
    if (c < G) dens[c] = 0.f;
    __syncthreads();

    int r0   = blockIdx.x * rpb;
    int rend = min(N, r0 + rpb);

    int row = r0;
    for (; row + 4 <= rend; row += 4) {
        float ev[4], xv[4];
        int   sg[4];
#pragma unroll
        for (int j = 0; j < 4; j++) {
            ev[j] = g_e[e_off + row + j];
            sg[j] = __ldg(lb + __ldg(ci0 + row + j));
            xv[j] = x[(size_t)(row + j) * FOLD + c];
        }
#pragma unroll
        for (int j = 0; j < 4; j++) {
            accs[sg[j] * 256 + c] += ev[j] * xv[j];
            if (c == 0) dens[sg[j]] += ev[j];
        }
    }
    for (; row < rend; ++row) {
        float ev = g_e[e_off + row];
        int   sg = __ldg(lb + __ldg(ci0 + row));
        accs[sg * 256 + c] += ev * x[(size_t)row * FOLD + c];
        if (c == 0) dens[sg] += ev;
    }
    __syncthreads();

    float* num = g_num + 2 * G * FOLD;
    for (int i = c; i < G * 256; i += 256) {
        float v = accs[i];
        if (v != 0.f) atomicAdd(num + i, v);
    }
    if (c < G) atomicAdd(g_den + 2 * G + c, dens[c]);
}

// ---------------------------------------------------------------------------
// Finalize: pooled = num/den, concat [G,768], 2-layer MLP + linear head.
__global__ __launch_bounds__(256) void mlp_kernel(
    const float* __restrict__ W1, const float* __restrict__ b1,
    const float* __restrict__ W2, const float* __restrict__ b2,
    const float* __restrict__ oW, const float* __restrict__ ob,
    float* __restrict__ out)
{
    __shared__ float comb[3 * FOLD];
    __shared__ float h1s[FOLD];
    __shared__ float h2s[HID];
    __shared__ float red[4];

    const int g = blockIdx.x, t = threadIdx.x;

    for (int i = t; i < 3 * FOLD; i += 256) {
        int p = i >> 8, cc = i & 255;
        comb[i] = g_num[(p * G + g) * FOLD + cc] / g_den[p * G + g];
    }
    __syncthreads();

    float h = b1[t];
    for (int k = 0; k < 3 * FOLD; k++)
        h = fmaf(comb[k], W1[(size_t)k * FOLD + t], h);
    h1s[t] = fmaxf(h, 0.f);
    __syncthreads();

    if (t < HID) {
        float h2 = b2[t];
        for (int k = 0; k < FOLD; k++)
            h2 = fmaf(h1s[k], W2[(size_t)k * HID + t], h2);
        h2s[t] = fmaxf(h2, 0.f);
    }
    __syncthreads();

    if (t < HID) {
        float v = h2s[t] * oW[t];
#pragma unroll
        for (int off = 16; off > 0; off >>= 1)
            v += __shfl_down_sync(0xffffffffu, v, off);
        if ((t & 31) == 0) red[t >> 5] = v;
    }
    __syncthreads();
    if (t == 0) out[g] = red[0] + red[1] + red[2] + red[3] + ob[0];
}

// ---------------------------------------------------------------------------
extern "C" void kernel_launch(void* const* d_in, const int* in_sizes, int n_in,
                              void* d_out, int out_size)
{
    const float* rec   = (const float*)d_in[0];
    const float* lig   = (const float*)d_in[1];
    const float* cross = (const float*)d_in[2];
    const int*   cidx  = (const int*)d_in[3];
    const int*   pb    = (const int*)d_in[4];
    const int*   lb    = (const int*)d_in[5];
    const float* paW1 = (const float*)d_in[7];
    const float* pab1 = (const float*)d_in[8];
    const float* paW2 = (const float*)d_in[9];
    const float* pab2 = (const float*)d_in[10];
    const float* laW1 = (const float*)d_in[11];
    const float* lab1 = (const float*)d_in[12];
    const float* laW2 = (const float*)d_in[13];
    const float* lab2 = (const float*)d_in[14];
    const float* caW1 = (const float*)d_in[15];
    const float* cab1 = (const float*)d_in[16];
    const float* caW2 = (const float*)d_in[17];
    const float* cab2 = (const float*)d_in[18];
    const float* mW1  = (const float*)d_in[19];
    const float* mb1  = (const float*)d_in[20];
    const float* mW2  = (const float*)d_in[21];
    const float* mb2  = (const float*)d_in[22];
    const float* oW   = (const float*)d_in[23];
    const float* ob   = (const float*)d_in[24];

    float* out = (float*)d_out;

    const int Np = in_sizes[0] / FOLD;
    const int Nl = in_sizes[1] / FOLD;
    const int Nc = in_sizes[2] / FOLD;
    const int eo_p = 0, eo_l = Np, eo_c = Np + Nl;

    static bool attr_done = false;
    if (!attr_done) {
        cudaFuncSetAttribute(scores_mma_kernel,
                             cudaFuncAttributeMaxDynamicSharedMemorySize, 66560);
        cudaFuncSetAttribute(pool_cross_kernel,
                             cudaFuncAttributeMaxDynamicSharedMemorySize,
                             (G * 256 + G) * (int)sizeof(float));
        attr_done = true;
    }

    zero_kernel<<<(3 * G * FOLD + 255) / 256, 256>>>();

    scores_mma_kernel<<<(Np + 127) / 128, 256, 66560>>>(rec,   Np, paW1, pab1, paW2, pab2, eo_p);
    scores_mma_kernel<<<(Nl + 127) / 128, 256, 66560>>>(lig,   Nl, laW1, lab1, laW2, lab2, eo_l);
    scores_mma_kernel<<<(Nc + 127) / 128, 256, 66560>>>(cross, Nc, caW1, cab1, caW2, cab2, eo_c);

    pool_sorted_kernel<<<(Np + 1023) / 1024, 256>>>(rec, pb, Np, eo_p, 0, 1024);
    pool_sorted_kernel<<<(Nl + 127) / 128,   256>>>(lig, lb, Nl, eo_l, 1, 128);

    const int rpb_c = 2048;
    pool_cross_kernel<<<(Nc + rpb_c - 1) / rpb_c, 256,
                        (G * 256 + G) * (int)sizeof(float)>>>(cross, cidx, lb, Nc, eo_c, rpb_c);

    mlp_kernel<<<G, 256>>>(mW1, mb1, mW2, mb2, oW, ob, out);
}

// round 3
// speedup vs baseline: 7.6078x; 1.7092x over previous
#include <cuda_runtime.h>
#include <cuda_bf16.h>
#include <cstdint>

#define G    64
#define FOLD 256
#define HID  128
#define TM   128   // rows per tile

// Scratch (device globals).
__device__ float g_num[3 * G * FOLD];
__device__ float g_den[3 * G];

// Smem layout (bytes)
#define OFF_AS    0            // 128 rows x 64 k bf16, 128B/row   = 16384
#define OFF_BS    16384        // 64 k x 128 n bf16, 256B/row      = 16384
#define OFF_ACCS  32768        // 64 x 256 f32                     = 65536
#define OFF_PART  98304        // 2 x 128 f32                      = 1024
#define OFF_ES    99328        // 128 f32                          = 512
#define OFF_SGS   99840        // 128 int                          = 512
#define OFF_DENS  100352       // 64 f32                           = 256
#define OFF_B1S   100608       // 128 f32                          = 512
#define OFF_W2S   101120       // 128 f32                          = 512
#define SMEM_SZ   101632

__global__ void zero_kernel() {
    int i = blockIdx.x * blockDim.x + threadIdx.x;
    if (i < 3 * G * FOLD) g_num[i] = 0.f;
    if (i < 3 * G)        g_den[i] = 0.f;
}

__device__ __forceinline__ uint32_t smem_u32(const void* p) {
    return (uint32_t)__cvta_generic_to_shared(p);
}
__device__ __forceinline__ uint32_t pack_bf16x2(float a, float b) {
    __nv_bfloat162 h = __floats2bfloat162_rn(a, b);
    return *reinterpret_cast<uint32_t*>(&h);
}

// ---------------------------------------------------------------------------
// Fused scores + attention-pool. Persistent blocks loop over 128-row tiles.
// GEMM: block m128 x n128, K=256 in 4 chunks of 64. 8 warps as 4m x 2n,
// warp tile m32 x n64, bf16 mma.sync with ldmatrix.x4 for A and B.
// Pool: smem [64 seg][256 col] accumulator, thread owns column, x re-read
// fp32 (L2-hot). Flush via atomics once per block.
__global__ __launch_bounds__(256, 2) void fused_kernel(
    const float* __restrict__ x, int N,
    const int* __restrict__ batch, const int* __restrict__ ci0,
    const int* __restrict__ lb, int indirect, int pool,
    const float* __restrict__ W1, const float* __restrict__ b1,
    const float* __restrict__ W2, const float* __restrict__ b2)
{
    extern __shared__ char smem[];
    char*  As   = smem + OFF_AS;
    char*  Bs   = smem + OFF_BS;
    float* accs = (float*)(smem + OFF_ACCS);
    float* part = (float*)(smem + OFF_PART);
    float* e_s  = (float*)(smem + OFF_ES);
    int*   sg_s = (int*)  (smem + OFF_SGS);
    float* dens = (float*)(smem + OFF_DENS);
    float* b1s  = (float*)(smem + OFF_B1S);
    float* w2s  = (float*)(smem + OFF_W2S);

    const int tid    = threadIdx.x;
    const int lane   = tid & 31;
    const int warp   = tid >> 5;
    const int warp_m = warp >> 1;       // 0..3  (m32 groups)
    const int wn     = warp & 1;        // 0..1  (n64 groups)
    const int m0     = warp_m * 32;

    for (int i = tid; i < G * FOLD; i += 256) accs[i] = 0.f;
    if (tid < G) dens[tid] = 0.f;
    if (tid < HID) { b1s[tid] = b1[tid]; w2s[tid] = W2[tid]; }
    const float b2v = b2[0];
    __syncthreads();

    const uint32_t as_base = smem_u32(As);
    const uint32_t bs_base = smem_u32(Bs);
    const int ntiles = (N + TM - 1) / TM;

    for (int tile = blockIdx.x; tile < ntiles; tile += gridDim.x) {
        const int row0 = tile * TM;

        float acc[2][8][4];
#pragma unroll
        for (int mi = 0; mi < 2; mi++)
#pragma unroll
            for (int ni = 0; ni < 8; ni++)
#pragma unroll
                for (int j = 0; j < 4; j++) acc[mi][ni][j] = 0.f;

#pragma unroll 1
        for (int kt = 0; kt < 4; kt++) {
            __syncthreads();    // prior mma reads / prior tile pooling done
            // A tile: 128 rows x 64 k (fp32 -> bf16), swizzled 16B chunks
#pragma unroll
            for (int i = 0; i < 4; i++) {
                int id = tid + i * 256;      // 1024 chunks
                int r  = id >> 3;
                int kc = id & 7;
                uint4 val = make_uint4(0u, 0u, 0u, 0u);
                int grow = row0 + r;
                if (grow < N) {
                    const float4* p = (const float4*)(x + (size_t)grow * FOLD + kt * 64 + kc * 8);
                    float4 f0 = p[0], f1 = p[1];
                    val.x = pack_bf16x2(f0.x, f0.y);
                    val.y = pack_bf16x2(f0.z, f0.w);
                    val.z = pack_bf16x2(f1.x, f1.y);
                    val.w = pack_bf16x2(f1.z, f1.w);
                }
                *(uint4*)(As + r * 128 + ((kc ^ (r & 7)) << 4)) = val;
            }
            // B tile: 64 k x 128 n
#pragma unroll
            for (int i = 0; i < 4; i++) {
                int id = tid + i * 256;
                int k  = id >> 4;
                int nc = id & 15;
                const float4* p = (const float4*)(W1 + (size_t)(kt * 64 + k) * HID + nc * 8);
                float4 f0 = p[0], f1 = p[1];
                uint4 val;
                val.x = pack_bf16x2(f0.x, f0.y);
                val.y = pack_bf16x2(f0.z, f0.w);
                val.z = pack_bf16x2(f1.x, f1.y);
                val.w = pack_bf16x2(f1.z, f1.w);
                *(uint4*)(Bs + k * 256 + ((nc ^ (k & 7)) << 4)) = val;
            }
            __syncthreads();

#pragma unroll
            for (int ks = 0; ks < 4; ks++) {
                uint32_t af[2][4];
#pragma unroll
                for (int mi = 0; mi < 2; mi++) {
                    int r  = m0 + mi * 16 + (lane & 7) + ((lane >> 3) & 1) * 8;
                    int kc = ks * 2 + (lane >> 4);
                    uint32_t addr = as_base + r * 128 + ((kc ^ (r & 7)) << 4);
                    asm volatile(
                        "ldmatrix.sync.aligned.m8n8.x4.shared.b16 {%0,%1,%2,%3}, [%4];"
                        : "=r"(af[mi][0]), "=r"(af[mi][1]), "=r"(af[mi][2]), "=r"(af[mi][3])
                        : "r"(addr));
                }
                uint32_t bf[8][2];
#pragma unroll
                for (int nj = 0; nj < 4; nj++) {
                    int k  = ks * 16 + (lane & 15);
                    int nc = wn * 8 + nj * 2 + (lane >> 4);
                    uint32_t addr = bs_base + k * 256 + ((nc ^ (k & 7)) << 4);
                    asm volatile(
                        "ldmatrix.sync.aligned.m8n8.x4.trans.shared.b16 {%0,%1,%2,%3}, [%4];"
                        : "=r"(bf[nj*2][0]), "=r"(bf[nj*2][1]),
                          "=r"(bf[nj*2+1][0]), "=r"(bf[nj*2+1][1])
                        : "r"(addr));
                }
#pragma unroll
                for (int mi = 0; mi < 2; mi++)
#pragma unroll
                    for (int ni = 0; ni < 8; ni++)
                        asm volatile(
                            "mma.sync.aligned.m16n8k16.row.col.f32.bf16.bf16.f32 "
                            "{%0,%1,%2,%3}, {%4,%5,%6,%7}, {%8,%9}, {%0,%1,%2,%3};"
                            : "+f"(acc[mi][ni][0]), "+f"(acc[mi][ni][1]),
                              "+f"(acc[mi][ni][2]), "+f"(acc[mi][ni][3])
                            : "r"(af[mi][0]), "r"(af[mi][1]), "r"(af[mi][2]), "r"(af[mi][3]),
                              "r"(bf[ni][0]), "r"(bf[ni][1]));
            }
        }

        // Epilogue: relu + second linear; per-warp n64 partial per row.
#pragma unroll
        for (int mi = 0; mi < 2; mi++) {
            float p1 = 0.f, p2 = 0.f;
            const int cb = (lane & 3) * 2;
#pragma unroll
            for (int ni = 0; ni < 8; ni++) {
                int c = wn * 64 + ni * 8 + cb;
                float w0 = w2s[c], w1v = w2s[c + 1];
                float q0 = b1s[c], q1 = b1s[c + 1];
                p1 += fmaxf(acc[mi][ni][0] + q0, 0.f) * w0 + fmaxf(acc[mi][ni][1] + q1, 0.f) * w1v;
                p2 += fmaxf(acc[mi][ni][2] + q0, 0.f) * w0 + fmaxf(acc[mi][ni][3] + q1, 0.f) * w1v;
            }
            p1 += __shfl_xor_sync(0xffffffffu, p1, 1);
            p1 += __shfl_xor_sync(0xffffffffu, p1, 2);
            p2 += __shfl_xor_sync(0xffffffffu, p2, 1);
            p2 += __shfl_xor_sync(0xffffffffu, p2, 2);
            if ((lane & 3) == 0) {
                int rl = m0 + mi * 16 + (lane >> 2);
                part[wn * 128 + rl]     = p1;
                part[wn * 128 + rl + 8] = p2;
            }
        }
        __syncthreads();

        if (tid < TM) {
            int row = row0 + tid;
            if (row < N) {
                float s = part[tid] + part[128 + tid] + b2v;
                e_s[tid]  = expf(s);
                sg_s[tid] = indirect ? __ldg(lb + __ldg(ci0 + row)) : __ldg(batch + row);
            } else {
                e_s[tid]  = 0.f;
                sg_s[tid] = 0;
            }
        }
        __syncthreads();

        // Pooling: thread owns column tid; register accumulation, flush on
        // segment change (sorted segments -> one flush per segment).
        const int rows = min(TM, N - row0);
        {
            const int c = tid;
            int   cur = sg_s[0];
            float a   = 0.f;
            int r = 0;
            for (; r + 4 <= rows; r += 4) {
                float xv[4];
#pragma unroll
                for (int j = 0; j < 4; j++)
                    xv[j] = __ldg(x + (size_t)(row0 + r + j) * FOLD + c);
#pragma unroll
                for (int j = 0; j < 4; j++) {
                    int   sg = sg_s[r + j];
                    float ev = e_s[r + j];
                    if (sg != cur) { accs[cur * FOLD + c] += a; a = 0.f; cur = sg; }
                    a = fmaf(ev, xv[j], a);
                }
            }
            for (; r < rows; ++r) {
                int   sg = sg_s[r];
                float ev = e_s[r];
                float xv = __ldg(x + (size_t)(row0 + r) * FOLD + c);
                if (sg != cur) { accs[cur * FOLD + c] += a; a = 0.f; cur = sg; }
                a = fmaf(ev, xv, a);
            }
            accs[cur * FOLD + c] += a;
        }
        // Denominators: 64 threads, masked scan over the tile's rows.
        if (tid < G) {
            float d = 0.f;
            for (int r = 0; r < rows; ++r)
                d += (sg_s[r] == tid) ? e_s[r] : 0.f;
            dens[tid] += d;
        }
    }

    __syncthreads();
    float* num = g_num + pool * G * FOLD;
    for (int i = tid; i < G * FOLD; i += 256) {
        float v = accs[i];
        if (v != 0.f) atomicAdd(num + i, v);
    }
    if (tid < G && dens[tid] != 0.f) atomicAdd(g_den + pool * G + tid, dens[tid]);
}

// ---------------------------------------------------------------------------
// Finalize: pooled = num/den, concat [G,768], 2-layer MLP + linear head.
__global__ __launch_bounds__(256) void mlp_kernel(
    const float* __restrict__ W1, const float* __restrict__ b1,
    const float* __restrict__ W2, const float* __restrict__ b2,
    const float* __restrict__ oW, const float* __restrict__ ob,
    float* __restrict__ out)
{
    __shared__ float comb[3 * FOLD];
    __shared__ float h1s[FOLD];
    __shared__ float h2s[HID];
    __shared__ float red[4];

    const int g = blockIdx.x, t = threadIdx.x;

    for (int i = t; i < 3 * FOLD; i += 256) {
        int p = i >> 8, cc = i & 255;
        comb[i] = g_num[(p * G + g) * FOLD + cc] / g_den[p * G + g];
    }
    __syncthreads();

    float h = b1[t];
    for (int k = 0; k < 3 * FOLD; k++)
        h = fmaf(comb[k], W1[(size_t)k * FOLD + t], h);
    h1s[t] = fmaxf(h, 0.f);
    __syncthreads();

    if (t < HID) {
        float h2 = b2[t];
        for (int k = 0; k < FOLD; k++)
            h2 = fmaf(h1s[k], W2[(size_t)k * HID + t], h2);
        h2s[t] = fmaxf(h2, 0.f);
    }
    __syncthreads();

    if (t < HID) {
        float v = h2s[t] * oW[t];
#pragma unroll
        for (int off = 16; off > 0; off >>= 1)
            v += __shfl_down_sync(0xffffffffu, v, off);
        if ((t & 31) == 0) red[t >> 5] = v;
    }
    __syncthreads();
    if (t == 0) out[g] = red[0] + red[1] + red[2] + red[3] + ob[0];
}

// ---------------------------------------------------------------------------
extern "C" void kernel_launch(void* const* d_in, const int* in_sizes, int n_in,
                              void* d_out, int out_size)
{
    const float* rec   = (const float*)d_in[0];
    const float* lig   = (const float*)d_in[1];
    const float* cross = (const float*)d_in[2];
    const int*   cidx  = (const int*)d_in[3];
    const int*   pb    = (const int*)d_in[4];
    const int*   lb    = (const int*)d_in[5];
    const float* paW1 = (const float*)d_in[7];
    const float* pab1 = (const float*)d_in[8];
    const float* paW2 = (const float*)d_in[9];
    const float* pab2 = (const float*)d_in[10];
    const float* laW1 = (const float*)d_in[11];
    const float* lab1 = (const float*)d_in[12];
    const float* laW2 = (const float*)d_in[13];
    const float* lab2 = (const float*)d_in[14];
    const float* caW1 = (const float*)d_in[15];
    const float* cab1 = (const float*)d_in[16];
    const float* caW2 = (const float*)d_in[17];
    const float* cab2 = (const float*)d_in[18];
    const float* mW1  = (const float*)d_in[19];
    const float* mb1  = (const float*)d_in[20];
    const float* mW2  = (const float*)d_in[21];
    const float* mb2  = (const float*)d_in[22];
    const float* oW   = (const float*)d_in[23];
    const float* ob   = (const float*)d_in[24];

    float* out = (float*)d_out;

    const int Np = in_sizes[0] / FOLD;
    const int Nl = in_sizes[1] / FOLD;
    const int Nc = in_sizes[2] / FOLD;

    static bool attr_done = false;
    if (!attr_done) {
        cudaFuncSetAttribute(fused_kernel,
                             cudaFuncAttributeMaxDynamicSharedMemorySize, SMEM_SZ);
        attr_done = true;
    }

    zero_kernel<<<(3 * G * FOLD + 255) / 256, 256>>>();

    const int maxb = 296;   // 2 blocks/SM x 148 SMs
    int gp = min((Np + TM - 1) / TM, maxb);
    int gl = min((Nl + TM - 1) / TM, maxb);
    int gc = min((Nc + TM - 1) / TM, maxb);

    fused_kernel<<<gp, 256, SMEM_SZ>>>(rec, Np, pb, nullptr, nullptr, 0, 0,
                                       paW1, pab1, paW2, pab2);
    fused_kernel<<<gl, 256, SMEM_SZ>>>(lig, Nl, lb, nullptr, nullptr, 0, 1,
                                       laW1, lab1, laW2, lab2);
    fused_kernel<<<gc, 256, SMEM_SZ>>>(cross, Nc, nullptr, cidx, lb, 1, 2,
                                       caW1, cab1, caW2, cab2);

    mlp_kernel<<<G, 256>>>(mW1, mb1, mW2, mb2, oW, ob, out);
}